// round 3
// baseline (speedup 1.0000x reference)
#include <cuda_runtime.h>

// Problem constants (fixed by the reference): B=8, C=64, H=W=256.
#define Bn   8
#define Cn   64
#define Hn   256
#define Wn   256
#define HWn  (Hn * Wn)          // 65536
#define NPIX (Bn * HWn)         // 524288 = 2^19
#define CPT  8                  // channels per thread
#define NCG  (Cn / CPT)         // 8 channel groups
#define PPT  4                  // pixels per thread (float4 vectorization)

__global__ __launch_bounds__(256)
void warp_bilinear_kernel(const float* __restrict__ phi,
                          const float* __restrict__ x_enc,
                          const float* __restrict__ m,
                          float* __restrict__ out)
{
    // cg in LOW bits of blockIdx -> all 8 channel groups of a pixel tile run
    // concurrently, so phi/m reads hit L2 for 7 of 8 groups.
    const int cg  = blockIdx.x & (NCG - 1);
    const int pg  = (blockIdx.x >> 3) * blockDim.x + threadIdx.x;  // pixel-group id
    const int b   = pg >> 14;                  // (HWn/PPT)=16384 groups per batch
    const int hwg = (pg & 16383) << 2;         // hw of first of 4 pixels
    const int h   = hwg >> 8;
    const int w   = hwg & (Wn - 1);            // first pixel's column (group of 4)

    // Vectorized per-pixel inputs (4 consecutive w, 16B aligned)
    const float4 pxv = *(const float4*)(phi + (b * 2 + 0) * HWn + hwg);
    const float4 pyv = *(const float4*)(phi + (b * 2 + 1) * HWn + hwg);
    const float4 mvv = *(const float4*)(m + b * HWn + hwg);
    const float* pxa = &pxv.x;
    const float* pya = &pyv.x;
    const float* mva = &mvv.x;

    float w00[PPT], w01[PPT], w10[PPT], w11[PPT];
    int   o00[PPT], o01[PPT], o10[PPT], o11[PPT];
    bool  anyv = false;

#pragma unroll
    for (int j = 0; j < PPT; ++j) {
        const float px = pxa[j];
        const float py = pya[j];
        const float mv = mva[j];

        // vgrid = 2*(coord+phi)/(dim-1) - 1 + 2*phi ; unnormalize (align_corners=False)
        const float vx = 2.0f * ((float)(w + j) + px) / (float)(Wn - 1) - 1.0f + 2.0f * px;
        const float vy = 2.0f * ((float)h + py) / (float)(Hn - 1) - 1.0f + 2.0f * py;
        const float ix = (vx + 1.0f) * (0.5f * (float)Wn) - 0.5f;
        const float iy = (vy + 1.0f) * (0.5f * (float)Hn) - 0.5f;

        const float x0f = floorf(ix);
        const float y0f = floorf(iy);
        const int   x0  = (int)x0f;
        const int   y0  = (int)y0f;
        const int   x1  = x0 + 1;
        const int   y1  = y0 + 1;

        const float wx1 = ix - x0f;
        const float wx0 = 1.0f - wx1;
        const float wy1 = iy - y0f;
        const float wy0 = 1.0f - wy1;

        const float vx0 = (x0 >= 0 && x0 < Wn) ? 1.0f : 0.0f;
        const float vx1 = (x1 >= 0 && x1 < Wn) ? 1.0f : 0.0f;
        const float vy0 = (y0 >= 0 && y0 < Hn) ? 1.0f : 0.0f;
        const float vy1 = (y1 >= 0 && y1 < Hn) ? 1.0f : 0.0f;

        // Fold validity AND mask into the 4 corner weights (zeros padding, out *= m)
        w00[j] = wy0 * wx0 * vy0 * vx0 * mv;
        w01[j] = wy0 * wx1 * vy0 * vx1 * mv;
        w10[j] = wy1 * wx0 * vy1 * vx0 * mv;
        w11[j] = wy1 * wx1 * vy1 * vx1 * mv;

        const int x0c = min(max(x0, 0), Wn - 1);
        const int x1c = min(max(x1, 0), Wn - 1);
        const int y0c = min(max(y0, 0), Hn - 1);
        const int y1c = min(max(y1, 0), Hn - 1);

        o00[j] = y0c * Wn + x0c;
        o01[j] = y0c * Wn + x1c;
        o10[j] = y1c * Wn + x0c;
        o11[j] = y1c * Wn + x1c;

        anyv |= (w00[j] != 0.0f) | (w01[j] != 0.0f) |
                (w10[j] != 0.0f) | (w11[j] != 0.0f);
    }

    const int baseC = (b * Cn + cg * CPT) * HWn;   // channel-plane base
    float* __restrict__ ob = out + baseC + hwg;

    if (!anyv) {
        // Common case (~96% of pixel groups): all 4 samples out-of-bounds or
        // masked -> 8 wide zero stores, no gathers.
        const float4 z = make_float4(0.0f, 0.0f, 0.0f, 0.0f);
#pragma unroll
        for (int c = 0; c < CPT; ++c)
            __stcs((float4*)(ob + c * HWn), z);
        return;
    }

    const float* __restrict__ xb = x_enc + baseC;

#pragma unroll
    for (int c = 0; c < CPT; ++c) {
        const float* __restrict__ p = xb + c * HWn;
        float4 v;
        float* va = &v.x;
#pragma unroll
        for (int j = 0; j < PPT; ++j) {
            float acc = 0.0f;
            if (w00[j] != 0.0f) acc = fmaf(w00[j], __ldg(p + o00[j]), acc);
            if (w01[j] != 0.0f) acc = fmaf(w01[j], __ldg(p + o01[j]), acc);
            if (w10[j] != 0.0f) acc = fmaf(w10[j], __ldg(p + o10[j]), acc);
            if (w11[j] != 0.0f) acc = fmaf(w11[j], __ldg(p + o11[j]), acc);
            va[j] = acc;
        }
        __stcs((float4*)(ob + c * HWn), v);
    }
}

extern "C" void kernel_launch(void* const* d_in, const int* in_sizes, int n_in,
                              void* d_out, int out_size)
{
    const float* phi   = (const float*)d_in[0];
    const float* x_enc = (const float*)d_in[1];
    const float* m     = (const float*)d_in[2];
    float* out         = (float*)d_out;

    const int total_threads = (NPIX / PPT) * NCG;  // 1,048,576
    const int tpb = 256;
    const int blocks = total_threads / tpb;        // 4096
    warp_bilinear_kernel<<<blocks, tpb>>>(phi, x_enc, m, out);
}